// round 1
// baseline (speedup 1.0000x reference)
#include <cuda_runtime.h>
#include <math.h>

// ---------------------------------------------------------------------------
// GatedDeltaNet (Qwen3-Next style), B=2, S=1024, H=2048, HV=32, HK=16,
// DK=DV=128, KW=4. All fp32.
// ---------------------------------------------------------------------------
#define BB   2
#define SS   1024
#define TT   (BB*SS)        // 2048 tokens
#define HH   2048
#define HV   32
#define HK   16
#define DK   128
#define DV   128
#define KW   4
#define KEY_DIM  (HK*DK)            // 2048
#define VAL_DIM  (HV*DV)            // 4096
#define CONV_DIM (2*KEY_DIM+VAL_DIM) // 8192

// ------------------------- scratch (device globals) ------------------------
__device__ float g_qkv_pre[TT * CONV_DIM];   // x @ Wqkv (pre-conv)
__device__ float g_mixed  [TT * CONV_DIM];   // after causal conv + silu
__device__ float g_z      [TT * VAL_DIM];    // x @ Wz
__device__ float g_qn     [TT * HV * DK];    // normalized, head-repeated q
__device__ float g_kn     [TT * HV * DK];
__device__ float g_g      [TT * HV];
__device__ float g_beta   [TT * HV];
__device__ float g_core   [TT * HV * DV];
__device__ float g_normed [TT * VAL_DIM];

// ---------------------------------------------------------------------------
// Classic 128x128x8 fp32 SGEMM, row-major A[M,K] * B[K,N] -> C[M,N].
// Requires M%128==0, N%128==0, K%8==0 (all true here).
// ---------------------------------------------------------------------------
__global__ __launch_bounds__(256) void sgemm128(
    const float* __restrict__ A, const float* __restrict__ B,
    float* __restrict__ C, int M, int N, int K)
{
    const int BM = 128, BN = 128, BK = 8;
    __shared__ float As[BK][BM];
    __shared__ float Bs[BK][BN];

    const int tid = threadIdx.x;
    const int bm = blockIdx.y * BM;
    const int bn = blockIdx.x * BN;

    const int arow = tid >> 1;          // 0..127
    const int acol = (tid & 1) * 4;     // 0 or 4
    const int brow = tid >> 5;          // 0..7
    const int bcol = (tid & 31) * 4;    // 0..124

    const int tr = tid >> 4;            // 0..15
    const int tc = tid & 15;            // 0..15

    float acc[8][8];
#pragma unroll
    for (int i = 0; i < 8; i++)
#pragma unroll
        for (int j = 0; j < 8; j++) acc[i][j] = 0.f;

    for (int k0 = 0; k0 < K; k0 += BK) {
        float4 av = *reinterpret_cast<const float4*>(A + (size_t)(bm + arow) * K + k0 + acol);
        As[acol + 0][arow] = av.x;
        As[acol + 1][arow] = av.y;
        As[acol + 2][arow] = av.z;
        As[acol + 3][arow] = av.w;
        *reinterpret_cast<float4*>(&Bs[brow][bcol]) =
            *reinterpret_cast<const float4*>(B + (size_t)(k0 + brow) * N + bn + bcol);
        __syncthreads();

#pragma unroll
        for (int kk = 0; kk < BK; kk++) {
            float ra[8], rb[8];
#pragma unroll
            for (int i = 0; i < 4; i++) {
                ra[i]     = As[kk][tr * 4 + i];
                ra[4 + i] = As[kk][64 + tr * 4 + i];
                rb[i]     = Bs[kk][tc * 4 + i];
                rb[4 + i] = Bs[kk][64 + tc * 4 + i];
            }
#pragma unroll
            for (int i = 0; i < 8; i++)
#pragma unroll
                for (int j = 0; j < 8; j++)
                    acc[i][j] += ra[i] * rb[j];
        }
        __syncthreads();
    }

#pragma unroll
    for (int i = 0; i < 8; i++) {
        int m = bm + ((i < 4) ? (tr * 4 + i) : (64 + tr * 4 + (i - 4)));
        float4 v0 = make_float4(acc[i][0], acc[i][1], acc[i][2], acc[i][3]);
        float4 v1 = make_float4(acc[i][4], acc[i][5], acc[i][6], acc[i][7]);
        *reinterpret_cast<float4*>(C + (size_t)m * N + bn + tc * 4)      = v0;
        *reinterpret_cast<float4*>(C + (size_t)m * N + bn + 64 + tc * 4) = v1;
    }
}

// ---------------------------------------------------------------------------
// Causal depthwise conv (KW=4) + SiLU.  pre: [T, CONV_DIM] -> mixed.
// ---------------------------------------------------------------------------
__global__ __launch_bounds__(256) void conv_silu(
    const float* __restrict__ pre, const float* __restrict__ cw,
    const float* __restrict__ cb, float* __restrict__ out)
{
    int c = blockIdx.x * 256 + threadIdx.x;    // channel
    int t = blockIdx.y;                        // token
    int b = t / SS, s = t % SS;
    float acc = cb[c];
#pragma unroll
    for (int j = 0; j < KW; j++) {
        int sp = s - (KW - 1) + j;
        if (sp >= 0)
            acc += pre[(size_t)(b * SS + sp) * CONV_DIM + c] * cw[c * KW + j];
    }
    // silu
    float o = acc / (1.f + expf(-acc));
    out[(size_t)t * CONV_DIM + c] = o;
}

// ---------------------------------------------------------------------------
// beta / g projections: x@Wb -> sigmoid, x@Wa -> g = -exp(A_log)*softplus(.+dt)
// One CTA per token. 256 threads: 64 outputs x 4 partial lanes.
// ---------------------------------------------------------------------------
__global__ __launch_bounds__(256) void proj_gb(
    const float* __restrict__ x, const float* __restrict__ Wb,
    const float* __restrict__ Wa, const float* __restrict__ dt_bias,
    const float* __restrict__ A_log, float* __restrict__ gout,
    float* __restrict__ bout)
{
    int t = blockIdx.x;
    __shared__ float xs[HH];
    const float4* xr = reinterpret_cast<const float4*>(x + (size_t)t * HH);
    float4* xs4 = reinterpret_cast<float4*>(xs);
    for (int i = threadIdx.x; i < HH / 4; i += 256) xs4[i] = xr[i];
    __syncthreads();

    int out  = threadIdx.x >> 2;   // 0..63
    int part = threadIdx.x & 3;    // 0..3
    const float* W = (out < 32) ? Wb : Wa;
    int col = out & 31;

    float acc = 0.f;
    int k0 = part * (HH / 4);
#pragma unroll 8
    for (int k = k0; k < k0 + HH / 4; k++)
        acc += xs[k] * W[k * HV + col];

    acc += __shfl_xor_sync(0xffffffffu, acc, 1);
    acc += __shfl_xor_sync(0xffffffffu, acc, 2);

    if (part == 0) {
        if (out < 32) {
            bout[t * HV + col] = 1.f / (1.f + expf(-acc));
        } else {
            float v = acc + dt_bias[col];
            float sp = (v > 20.f) ? v : log1pf(expf(v));
            gout[t * HV + col] = -expf(A_log[col]) * sp;
        }
    }
}

// ---------------------------------------------------------------------------
// q/k l2-normalization (+ q * DK^-0.5), head-repeat HK->HV.
// One CTA per (t, hk). 128 threads (one per dk).
// ---------------------------------------------------------------------------
__global__ __launch_bounds__(128) void qk_prep(
    const float* __restrict__ mixed, float* __restrict__ qn,
    float* __restrict__ kn)
{
    int blk = blockIdx.x;
    int t = blk / HK, hk = blk % HK;
    int dk = threadIdx.x;

    float qv = mixed[(size_t)t * CONV_DIM + hk * DK + dk];
    float kv = mixed[(size_t)t * CONV_DIM + KEY_DIM + hk * DK + dk];

    __shared__ float s1[128], s2[128];
    s1[dk] = qv * qv;
    s2[dk] = kv * kv;
    __syncthreads();
#pragma unroll
    for (int off = 64; off > 0; off >>= 1) {
        if (dk < off) { s1[dk] += s1[dk + off]; s2[dk] += s2[dk + off]; }
        __syncthreads();
    }
    __shared__ float rq, rk;
    if (dk == 0) {
        rq = rsqrtf(s1[0] + 1e-6f);
        rk = rsqrtf(s2[0] + 1e-6f);
    }
    __syncthreads();

    float qo = qv * rq * 0.08838834764831845f;   // * DK^-0.5
    float ko = kv * rk;
    int h0 = hk * 2;
    size_t base0 = ((size_t)t * HV + h0) * DK + dk;
    size_t base1 = ((size_t)t * HV + h0 + 1) * DK + dk;
    qn[base0] = qo; qn[base1] = qo;
    kn[base0] = ko; kn[base1] = ko;
}

// ---------------------------------------------------------------------------
// Gated delta-rule recurrence. One CTA per (b, h); thread dv owns the full
// 128-deep state column state[0..127][dv] in registers.
// ---------------------------------------------------------------------------
__global__ __launch_bounds__(128) void recurrence(
    const float* __restrict__ qn, const float* __restrict__ kn,
    const float* __restrict__ mixed, const float* __restrict__ gg,
    const float* __restrict__ bb, float* __restrict__ core)
{
    int bh = blockIdx.x;            // b*HV + h
    int b = bh / HV, h = bh % HV;
    int dv = threadIdx.x;

    float st[DK];
#pragma unroll
    for (int i = 0; i < DK; i++) st[i] = 0.f;

    __shared__ float ks[DK], qs[DK];

    for (int s = 0; s < SS; s++) {
        int t = b * SS + s;
        __syncthreads();
        ks[dv] = kn[((size_t)t * HV + h) * DK + dv];
        qs[dv] = qn[((size_t)t * HV + h) * DK + dv];
        __syncthreads();

        float gv  = gg[t * HV + h];
        float bv  = bb[t * HV + h];
        float dec = expf(gv);
        float vv  = mixed[(size_t)t * CONV_DIM + 2 * KEY_DIM + h * DV + dv];

        float m0 = 0.f, m1 = 0.f, m2 = 0.f, m3 = 0.f;
#pragma unroll
        for (int i = 0; i < DK; i += 4) {
            float4 kk = *reinterpret_cast<const float4*>(&ks[i]);
            st[i + 0] *= dec; m0 += kk.x * st[i + 0];
            st[i + 1] *= dec; m1 += kk.y * st[i + 1];
            st[i + 2] *= dec; m2 += kk.z * st[i + 2];
            st[i + 3] *= dec; m3 += kk.w * st[i + 3];
        }
        float mem = (m0 + m1) + (m2 + m3);
        float delta = (vv - mem) * bv;

        float o0 = 0.f, o1 = 0.f, o2 = 0.f, o3 = 0.f;
#pragma unroll
        for (int i = 0; i < DK; i += 4) {
            float4 kk = *reinterpret_cast<const float4*>(&ks[i]);
            float4 qq = *reinterpret_cast<const float4*>(&qs[i]);
            st[i + 0] += kk.x * delta; o0 += qq.x * st[i + 0];
            st[i + 1] += kk.y * delta; o1 += qq.y * st[i + 1];
            st[i + 2] += kk.z * delta; o2 += qq.z * st[i + 2];
            st[i + 3] += kk.w * delta; o3 += qq.w * st[i + 3];
        }
        core[((size_t)t * HV + h) * DV + dv] = (o0 + o1) + (o2 + o3);
    }
}

// ---------------------------------------------------------------------------
// gated RMSNorm: gated = core * silu(z); normed = gated * rsqrt(mean(g^2)+eps)*w
// One CTA per (t, h), 128 threads.
// ---------------------------------------------------------------------------
__global__ __launch_bounds__(128) void gated_norm(
    const float* __restrict__ core, const float* __restrict__ z,
    const float* __restrict__ nw, float* __restrict__ normed)
{
    int bh = blockIdx.x;   // t*HV + h
    int dv = threadIdx.x;
    size_t idx = (size_t)bh * DV + dv;

    float c  = core[idx];
    float zv = z[idx];
    float gz = c * (zv / (1.f + expf(-zv)));

    __shared__ float red[128];
    red[dv] = gz * gz;
    __syncthreads();
#pragma unroll
    for (int off = 64; off > 0; off >>= 1) {
        if (dv < off) red[dv] += red[dv + off];
        __syncthreads();
    }
    __shared__ float rs;
    if (dv == 0) rs = rsqrtf(red[0] * (1.f / DV) + 1e-6f);
    __syncthreads();

    normed[idx] = gz * rs * nw[dv];
}

// ---------------------------------------------------------------------------
// launch
// ---------------------------------------------------------------------------
extern "C" void kernel_launch(void* const* d_in, const int* in_sizes, int n_in,
                              void* d_out, int out_size)
{
    const float* x        = (const float*)d_in[0];   // [B,S,H]
    const float* Wqkv     = (const float*)d_in[1];   // [H, CONV_DIM]
    const float* Wz       = (const float*)d_in[2];   // [H, VAL_DIM]
    const float* Wb       = (const float*)d_in[3];   // [H, HV]
    const float* Wa       = (const float*)d_in[4];   // [H, HV]
    const float* conv_w   = (const float*)d_in[5];   // [CONV_DIM, KW]
    const float* conv_b   = (const float*)d_in[6];   // [CONV_DIM]
    const float* dt_bias  = (const float*)d_in[7];   // [HV]
    const float* A_log    = (const float*)d_in[8];   // [HV]
    const float* norm_w   = (const float*)d_in[9];   // [DV]
    const float* Wout     = (const float*)d_in[10];  // [VAL_DIM, H]
    float* out = (float*)d_out;

    float *qkv_pre, *mixed, *z, *qn, *kn, *gbuf, *bbuf, *core, *normed;
    cudaGetSymbolAddress((void**)&qkv_pre, g_qkv_pre);
    cudaGetSymbolAddress((void**)&mixed,   g_mixed);
    cudaGetSymbolAddress((void**)&z,       g_z);
    cudaGetSymbolAddress((void**)&qn,      g_qn);
    cudaGetSymbolAddress((void**)&kn,      g_kn);
    cudaGetSymbolAddress((void**)&gbuf,    g_g);
    cudaGetSymbolAddress((void**)&bbuf,    g_beta);
    cudaGetSymbolAddress((void**)&core,    g_core);
    cudaGetSymbolAddress((void**)&normed,  g_normed);

    // 1) big projections
    sgemm128<<<dim3(CONV_DIM / 128, TT / 128), 256>>>(x, Wqkv, qkv_pre, TT, CONV_DIM, HH);
    sgemm128<<<dim3(VAL_DIM / 128, TT / 128), 256>>>(x, Wz, z, TT, VAL_DIM, HH);
    proj_gb<<<TT, 256>>>(x, Wb, Wa, dt_bias, A_log, gbuf, bbuf);

    // 2) causal conv + silu
    conv_silu<<<dim3(CONV_DIM / 256, TT), 256>>>(qkv_pre, conv_w, conv_b, mixed);

    // 3) q/k norm + repeat
    qk_prep<<<TT * HK, 128>>>(mixed, qn, kn);

    // 4) recurrence
    recurrence<<<BB * HV, 128>>>(qn, kn, mixed, gbuf, bbuf, core);

    // 5) gated RMSNorm
    gated_norm<<<TT * HV, 128>>>(core, z, norm_w, normed);

    // 6) output projection
    sgemm128<<<dim3(HH / 128, TT / 128), 256>>>(normed, Wout, out, TT, HH, VAL_DIM);
}

// round 2
// speedup vs baseline: 2.3128x; 2.3128x over previous
#include <cuda_runtime.h>
#include <math.h>
#include <stdint.h>

// ---------------------------------------------------------------------------
// GatedDeltaNet (Qwen3-Next style), B=2, S=1024, H=2048, HV=32, HK=16,
// DK=DV=128, KW=4.  tf32 tensor-core GEMMs + fp32 everything else.
// ---------------------------------------------------------------------------
#define BB   2
#define SS   1024
#define TT   (BB*SS)        // 2048 tokens
#define HH   2048
#define HV   32
#define HK   16
#define DK   128
#define DV   128
#define KW   4
#define KEY_DIM  (HK*DK)             // 2048
#define VAL_DIM  (HV*DV)             // 4096
#define CONV_DIM (2*KEY_DIM+VAL_DIM) // 8192

// ------------------------- scratch (device globals) ------------------------
__device__ float g_qkv_pre[TT * CONV_DIM];   // x @ Wqkv (pre-conv)
__device__ float g_mixed  [TT * CONV_DIM];   // after causal conv + silu
__device__ float g_z      [TT * VAL_DIM];    // x @ Wz
__device__ float g_qn     [TT * HV * DK];    // normalized, head-repeated q
__device__ float g_kn     [TT * HV * DK];
__device__ float g_g      [TT * HV];
__device__ float g_beta   [TT * HV];
__device__ float g_core   [TT * HV * DV];
__device__ float g_normed [TT * VAL_DIM];    // tf32-rounded
// tf32-rounded operand copies
__device__ float g_x_r    [TT * HH];
__device__ float g_Wqkv_r [HH * CONV_DIM];
__device__ float g_Wz_r   [HH * VAL_DIM];
__device__ float g_Wout_r [VAL_DIM * HH];

// ---------------------------------------------------------------------------
// elementwise cvt.rna.tf32 pre-rounding (float4 vectorized)
// ---------------------------------------------------------------------------
__device__ __forceinline__ float tf32r(float x) {
    uint32_t u;
    asm("cvt.rna.tf32.f32 %0, %1;" : "=r"(u) : "f"(x));
    return __uint_as_float(u);
}

__global__ __launch_bounds__(256) void tf32_round(
    const float4* __restrict__ in, float4* __restrict__ out, int n4)
{
    int i = blockIdx.x * 256 + threadIdx.x;
    if (i >= n4) return;
    float4 v = in[i];
    v.x = tf32r(v.x); v.y = tf32r(v.y); v.z = tf32r(v.z); v.w = tf32r(v.w);
    out[i] = v;
}

// ---------------------------------------------------------------------------
// tf32 tensor-core GEMM: C[M,N] = A[M,K] * B[K,N], row-major, fp32 I/O
// (A,B must be pre-rounded to tf32).  M%128==0, N%128==0, K%32==0.
// CTA tile 128x128x32, 256 threads = 8 warps of 64x32, double-buffered
// cp.async, conflict-free smem (A: pad-4 m-major, B: xor-8 swizzle).
// ---------------------------------------------------------------------------
#define MMA_TF32(d, av, bv)                                                    \
    asm volatile("mma.sync.aligned.m16n8k8.row.col.f32.tf32.tf32.f32 "         \
                 "{%0,%1,%2,%3},{%4,%5,%6,%7},{%8,%9},{%0,%1,%2,%3};"          \
                 : "+f"(d[0]), "+f"(d[1]), "+f"(d[2]), "+f"(d[3])              \
                 : "r"(av[0]), "r"(av[1]), "r"(av[2]), "r"(av[3]),             \
                   "r"(bv[0]), "r"(bv[1]))

#define CP16(dst, src)                                                         \
    asm volatile("cp.async.cg.shared.global [%0], [%1], 16;" ::                \
                 "r"(dst), "l"(src))

__global__ __launch_bounds__(256) void gemm_tf32(
    const float* __restrict__ A, const float* __restrict__ B,
    float* __restrict__ C, int M, int N, int K)
{
    extern __shared__ float smem[];
    float* sA = smem;                  // [2][128][36]
    float* sB = smem + 2 * 128 * 36;   // [2][32][128]
    const uint32_t smem_base = (uint32_t)__cvta_generic_to_shared(smem);
    const uint32_t sB_base   = smem_base + 2u * 128u * 36u * 4u;

    const int tid  = threadIdx.x;
    const int lane = tid & 31;
    const int wid  = tid >> 5;
    const int wm   = (wid >> 2) * 64;      // warp m offset (0/64)
    const int wn   = (wid & 3) * 32;       // warp n offset (0/32/64/96)
    const int g    = lane >> 2;            // 0..7
    const int tig  = lane & 3;             // 0..3
    const int bm   = blockIdx.y * 128;
    const int bn   = blockIdx.x * 128;

    // global-load indexing
    const int ar = tid >> 3;               // A base row 0..31 (+0/32/64/96)
    const int ak = (tid & 7) * 4;          // A k chunk
    const int br = tid >> 5;               // B base row 0..7 (+0/8/16/24)
    const int bc = lane * 4;               // B n chunk 0..124

    const float* Ag = A + (size_t)(bm + ar) * K + ak;
    const float* Bg = B + (size_t)br * N + bn + bc;

    float acc[4][4][4];
#pragma unroll
    for (int mf = 0; mf < 4; mf++)
#pragma unroll
        for (int nf = 0; nf < 4; nf++)
#pragma unroll
            for (int i = 0; i < 4; i++) acc[mf][nf][i] = 0.f;

    const int nt = K / 32;

#define LOAD_TILE(kt, buf) do {                                                \
        _Pragma("unroll")                                                      \
        for (int i = 0; i < 4; i++) {                                          \
            uint32_t d = smem_base +                                           \
                ((buf) * (128 * 36) + (ar + 32 * i) * 36 + ak) * 4u;           \
            const float* s = Ag + (size_t)(32 * i) * K + (size_t)(kt) * 32;    \
            CP16(d, s);                                                        \
        }                                                                      \
        _Pragma("unroll")                                                      \
        for (int i = 0; i < 4; i++) {                                          \
            int row = br + 8 * i;                                              \
            int csw = bc ^ ((row & 3) * 8);                                    \
            uint32_t d = sB_base + ((buf) * (32 * 128) + row * 128 + csw) * 4u;\
            const float* s = Bg + (size_t)((kt) * 32 + 8 * i) * N;             \
            CP16(d, s);                                                        \
        }                                                                      \
        asm volatile("cp.async.commit_group;");                                \
    } while (0)

    LOAD_TILE(0, 0);
    LOAD_TILE(1, 1);
    asm volatile("cp.async.wait_group 1;");
    __syncthreads();

    for (int t = 0; t < nt; t++) {
        const int buf = t & 1;
        const float* cA = sA + buf * (128 * 36);
        const float* cB = sB + buf * (32 * 128);

#pragma unroll
        for (int ks = 0; ks < 4; ks++) {
            uint32_t afr[4][4];
            uint32_t bfr[4][2];
            const int k = ks * 8 + tig;
#pragma unroll
            for (int mf = 0; mf < 4; mf++) {
                int r = wm + mf * 16 + g;
                afr[mf][0] = __float_as_uint(cA[r * 36 + k]);
                afr[mf][1] = __float_as_uint(cA[(r + 8) * 36 + k]);
                afr[mf][2] = __float_as_uint(cA[r * 36 + k + 4]);
                afr[mf][3] = __float_as_uint(cA[(r + 8) * 36 + k + 4]);
            }
            const int r0 = ks * 8 + tig, r1 = r0 + 4;
            const int sw = tig * 8;
#pragma unroll
            for (int nf = 0; nf < 4; nf++) {
                int c = wn + nf * 8 + g;
                bfr[nf][0] = __float_as_uint(cB[r0 * 128 + (c ^ sw)]);
                bfr[nf][1] = __float_as_uint(cB[r1 * 128 + (c ^ sw)]);
            }
#pragma unroll
            for (int mf = 0; mf < 4; mf++)
#pragma unroll
                for (int nf = 0; nf < 4; nf++)
                    MMA_TF32(acc[mf][nf], afr[mf], bfr[nf]);
        }

        __syncthreads();
        if (t + 2 < nt) {
            LOAD_TILE(t + 2, buf);
            asm volatile("cp.async.wait_group 1;");
        } else {
            asm volatile("cp.async.wait_group 0;");
        }
        __syncthreads();
    }

    // epilogue
#pragma unroll
    for (int mf = 0; mf < 4; mf++) {
#pragma unroll
        for (int nf = 0; nf < 4; nf++) {
            int r = bm + wm + mf * 16 + g;
            int c = bn + wn + nf * 8 + tig * 2;
            *reinterpret_cast<float2*>(C + (size_t)r * N + c) =
                make_float2(acc[mf][nf][0], acc[mf][nf][1]);
            *reinterpret_cast<float2*>(C + (size_t)(r + 8) * N + c) =
                make_float2(acc[mf][nf][2], acc[mf][nf][3]);
        }
    }
#undef LOAD_TILE
}

// ---------------------------------------------------------------------------
// Causal depthwise conv (KW=4) + SiLU.  pre: [T, CONV_DIM] -> mixed.
// ---------------------------------------------------------------------------
__global__ __launch_bounds__(256) void conv_silu(
    const float* __restrict__ pre, const float* __restrict__ cw,
    const float* __restrict__ cb, float* __restrict__ out)
{
    int c = blockIdx.x * 256 + threadIdx.x;    // channel
    int t = blockIdx.y;                        // token
    int b = t / SS, s = t % SS;
    float acc = cb[c];
#pragma unroll
    for (int j = 0; j < KW; j++) {
        int sp = s - (KW - 1) + j;
        if (sp >= 0)
            acc += pre[(size_t)(b * SS + sp) * CONV_DIM + c] * cw[c * KW + j];
    }
    float o = acc / (1.f + expf(-acc));
    out[(size_t)t * CONV_DIM + c] = o;
}

// ---------------------------------------------------------------------------
// beta / g projections
// ---------------------------------------------------------------------------
__global__ __launch_bounds__(256) void proj_gb(
    const float* __restrict__ x, const float* __restrict__ Wb,
    const float* __restrict__ Wa, const float* __restrict__ dt_bias,
    const float* __restrict__ A_log, float* __restrict__ gout,
    float* __restrict__ bout)
{
    int t = blockIdx.x;
    __shared__ float xs[HH];
    const float4* xr = reinterpret_cast<const float4*>(x + (size_t)t * HH);
    float4* xs4 = reinterpret_cast<float4*>(xs);
    for (int i = threadIdx.x; i < HH / 4; i += 256) xs4[i] = xr[i];
    __syncthreads();

    int out  = threadIdx.x >> 2;   // 0..63
    int part = threadIdx.x & 3;    // 0..3
    const float* W = (out < 32) ? Wb : Wa;
    int col = out & 31;

    float acc = 0.f;
    int k0 = part * (HH / 4);
#pragma unroll 8
    for (int k = k0; k < k0 + HH / 4; k++)
        acc += xs[k] * W[k * HV + col];

    acc += __shfl_xor_sync(0xffffffffu, acc, 1);
    acc += __shfl_xor_sync(0xffffffffu, acc, 2);

    if (part == 0) {
        if (out < 32) {
            bout[t * HV + col] = 1.f / (1.f + expf(-acc));
        } else {
            float v = acc + dt_bias[col];
            float sp = (v > 20.f) ? v : log1pf(expf(v));
            gout[t * HV + col] = -expf(A_log[col]) * sp;
        }
    }
}

// ---------------------------------------------------------------------------
// q/k l2-normalization (+ q * DK^-0.5), head-repeat HK->HV.
// ---------------------------------------------------------------------------
__global__ __launch_bounds__(128) void qk_prep(
    const float* __restrict__ mixed, float* __restrict__ qn,
    float* __restrict__ kn)
{
    int blk = blockIdx.x;
    int t = blk / HK, hk = blk % HK;
    int dk = threadIdx.x;

    float qv = mixed[(size_t)t * CONV_DIM + hk * DK + dk];
    float kv = mixed[(size_t)t * CONV_DIM + KEY_DIM + hk * DK + dk];

    __shared__ float s1[128], s2[128];
    s1[dk] = qv * qv;
    s2[dk] = kv * kv;
    __syncthreads();
#pragma unroll
    for (int off = 64; off > 0; off >>= 1) {
        if (dk < off) { s1[dk] += s1[dk + off]; s2[dk] += s2[dk + off]; }
        __syncthreads();
    }
    __shared__ float rq, rk;
    if (dk == 0) {
        rq = rsqrtf(s1[0] + 1e-6f);
        rk = rsqrtf(s2[0] + 1e-6f);
    }
    __syncthreads();

    float qo = qv * rq * 0.08838834764831845f;   // * DK^-0.5
    float ko = kv * rk;
    int h0 = hk * 2;
    size_t base0 = ((size_t)t * HV + h0) * DK + dk;
    size_t base1 = ((size_t)t * HV + h0 + 1) * DK + dk;
    qn[base0] = qo; qn[base1] = qo;
    kn[base0] = ko; kn[base1] = ko;
}

// ---------------------------------------------------------------------------
// Gated delta-rule recurrence. One CTA per (b, h); thread dv owns the full
// 128-deep state column in registers. Double-buffered k/q smem, 1 bar/step.
// ---------------------------------------------------------------------------
__global__ __launch_bounds__(128) void recurrence(
    const float* __restrict__ qn, const float* __restrict__ kn,
    const float* __restrict__ mixed, const float* __restrict__ gg,
    const float* __restrict__ bb, float* __restrict__ core)
{
    int bh = blockIdx.x;            // b*HV + h
    int b = bh / HV, h = bh % HV;
    int dv = threadIdx.x;

    float st[DK];
#pragma unroll
    for (int i = 0; i < DK; i++) st[i] = 0.f;

    __shared__ float ks[2][DK], qs[2][DK];

    // preload step 0
    int t0 = b * SS;
    ks[0][dv] = kn[((size_t)t0 * HV + h) * DK + dv];
    qs[0][dv] = qn[((size_t)t0 * HV + h) * DK + dv];
    float gv = gg[t0 * HV + h];
    float bv = bb[t0 * HV + h];
    float vv = mixed[(size_t)t0 * CONV_DIM + 2 * KEY_DIM + h * DV + dv];
    __syncthreads();

    for (int s = 0; s < SS; s++) {
        const int cur = s & 1;
        const int t = b * SS + s;

        // prefetch next step's operands (hidden under compute)
        float knx = 0.f, qnx = 0.f, gnx = 0.f, bnx = 0.f, vnx = 0.f;
        if (s + 1 < SS) {
            int tn = t + 1;
            knx = kn[((size_t)tn * HV + h) * DK + dv];
            qnx = qn[((size_t)tn * HV + h) * DK + dv];
            gnx = gg[tn * HV + h];
            bnx = bb[tn * HV + h];
            vnx = mixed[(size_t)tn * CONV_DIM + 2 * KEY_DIM + h * DV + dv];
        }

        float dec = expf(gv);

        float m0 = 0.f, m1 = 0.f, m2 = 0.f, m3 = 0.f;
#pragma unroll
        for (int i = 0; i < DK; i += 4) {
            float4 kk = *reinterpret_cast<const float4*>(&ks[cur][i]);
            st[i + 0] *= dec; m0 += kk.x * st[i + 0];
            st[i + 1] *= dec; m1 += kk.y * st[i + 1];
            st[i + 2] *= dec; m2 += kk.z * st[i + 2];
            st[i + 3] *= dec; m3 += kk.w * st[i + 3];
        }
        float mem = (m0 + m1) + (m2 + m3);
        float delta = (vv - mem) * bv;

        float o0 = 0.f, o1 = 0.f, o2 = 0.f, o3 = 0.f;
#pragma unroll
        for (int i = 0; i < DK; i += 4) {
            float4 kk = *reinterpret_cast<const float4*>(&ks[cur][i]);
            float4 qq = *reinterpret_cast<const float4*>(&qs[cur][i]);
            st[i + 0] += kk.x * delta; o0 += qq.x * st[i + 0];
            st[i + 1] += kk.y * delta; o1 += qq.y * st[i + 1];
            st[i + 2] += kk.z * delta; o2 += qq.z * st[i + 2];
            st[i + 3] += kk.w * delta; o3 += qq.w * st[i + 3];
        }
        core[((size_t)t * HV + h) * DV + dv] = (o0 + o1) + (o2 + o3);

        // stage next step
        if (s + 1 < SS) {
            ks[cur ^ 1][dv] = knx;
            qs[cur ^ 1][dv] = qnx;
        }
        gv = gnx; bv = bnx; vv = vnx;
        __syncthreads();
    }
}

// ---------------------------------------------------------------------------
// gated RMSNorm; emits tf32-rounded output (feeds the out-projection MMA).
// ---------------------------------------------------------------------------
__global__ __launch_bounds__(128) void gated_norm(
    const float* __restrict__ core, const float* __restrict__ z,
    const float* __restrict__ nw, float* __restrict__ normed)
{
    int bh = blockIdx.x;   // t*HV + h
    int dv = threadIdx.x;
    size_t idx = (size_t)bh * DV + dv;

    float c  = core[idx];
    float zv = z[idx];
    float gz = c * (zv / (1.f + expf(-zv)));

    __shared__ float red[128];
    red[dv] = gz * gz;
    __syncthreads();
#pragma unroll
    for (int off = 64; off > 0; off >>= 1) {
        if (dv < off) red[dv] += red[dv + off];
        __syncthreads();
    }
    __shared__ float rs;
    if (dv == 0) rs = rsqrtf(red[0] * (1.f / DV) + 1e-6f);
    __syncthreads();

    normed[idx] = tf32r(gz * rs * nw[dv]);
}

// ---------------------------------------------------------------------------
// launch
// ---------------------------------------------------------------------------
extern "C" void kernel_launch(void* const* d_in, const int* in_sizes, int n_in,
                              void* d_out, int out_size)
{
    const float* x        = (const float*)d_in[0];   // [B,S,H]
    const float* Wqkv     = (const float*)d_in[1];   // [H, CONV_DIM]
    const float* Wz       = (const float*)d_in[2];   // [H, VAL_DIM]
    const float* Wb       = (const float*)d_in[3];   // [H, HV]
    const float* Wa       = (const float*)d_in[4];   // [H, HV]
    const float* conv_w   = (const float*)d_in[5];   // [CONV_DIM, KW]
    const float* conv_b   = (const float*)d_in[6];   // [CONV_DIM]
    const float* dt_bias  = (const float*)d_in[7];   // [HV]
    const float* A_log    = (const float*)d_in[8];   // [HV]
    const float* norm_w   = (const float*)d_in[9];   // [DV]
    const float* Wout     = (const float*)d_in[10];  // [VAL_DIM, H]
    float* out = (float*)d_out;

    float *qkv_pre, *mixed, *z, *qn, *kn, *gbuf, *bbuf, *core, *normed;
    float *x_r, *Wqkv_r, *Wz_r, *Wout_r;
    cudaGetSymbolAddress((void**)&qkv_pre, g_qkv_pre);
    cudaGetSymbolAddress((void**)&mixed,   g_mixed);
    cudaGetSymbolAddress((void**)&z,       g_z);
    cudaGetSymbolAddress((void**)&qn,      g_qn);
    cudaGetSymbolAddress((void**)&kn,      g_kn);
    cudaGetSymbolAddress((void**)&gbuf,    g_g);
    cudaGetSymbolAddress((void**)&bbuf,    g_beta);
    cudaGetSymbolAddress((void**)&core,    g_core);
    cudaGetSymbolAddress((void**)&normed,  g_normed);
    cudaGetSymbolAddress((void**)&x_r,     g_x_r);
    cudaGetSymbolAddress((void**)&Wqkv_r,  g_Wqkv_r);
    cudaGetSymbolAddress((void**)&Wz_r,    g_Wz_r);
    cudaGetSymbolAddress((void**)&Wout_r,  g_Wout_r);

    const int SMEM_BYTES = (2 * 128 * 36 + 2 * 32 * 128) * 4;   // 69632
    static int smem_set = 0;
    if (!smem_set) {
        cudaFuncSetAttribute(gemm_tf32,
            cudaFuncAttributeMaxDynamicSharedMemorySize, SMEM_BYTES);
        smem_set = 1;
    }

    // 0) tf32 pre-rounding of GEMM operands
    tf32_round<<<(TT * HH / 4) / 256, 256>>>(
        (const float4*)x, (float4*)x_r, TT * HH / 4);
    tf32_round<<<(HH * CONV_DIM / 4) / 256, 256>>>(
        (const float4*)Wqkv, (float4*)Wqkv_r, HH * CONV_DIM / 4);
    tf32_round<<<(HH * VAL_DIM / 4) / 256, 256>>>(
        (const float4*)Wz, (float4*)Wz_r, HH * VAL_DIM / 4);
    tf32_round<<<(VAL_DIM * HH / 4) / 256, 256>>>(
        (const float4*)Wout, (float4*)Wout_r, VAL_DIM * HH / 4);

    // 1) big projections (tensor cores)
    gemm_tf32<<<dim3(CONV_DIM / 128, TT / 128), 256, SMEM_BYTES>>>(
        x_r, Wqkv_r, qkv_pre, TT, CONV_DIM, HH);
    gemm_tf32<<<dim3(VAL_DIM / 128, TT / 128), 256, SMEM_BYTES>>>(
        x_r, Wz_r, z, TT, VAL_DIM, HH);
    proj_gb<<<TT, 256>>>(x, Wb, Wa, dt_bias, A_log, gbuf, bbuf);

    // 2) causal conv + silu
    conv_silu<<<dim3(CONV_DIM / 256, TT), 256>>>(qkv_pre, conv_w, conv_b, mixed);

    // 3) q/k norm + repeat
    qk_prep<<<TT * HK, 128>>>(mixed, qn, kn);

    // 4) recurrence
    recurrence<<<BB * HV, 128>>>(qn, kn, mixed, gbuf, bbuf, core);

    // 5) gated RMSNorm (emits tf32-rounded)
    gated_norm<<<TT * HV, 128>>>(core, z, norm_w, normed);

    // 6) output projection (tensor cores)
    gemm_tf32<<<dim3(HH / 128, TT / 128), 256, SMEM_BYTES>>>(
        normed, Wout_r, out, TT, HH, VAL_DIM);
}